// round 4
// baseline (speedup 1.0000x reference)
#include <cuda_runtime.h>
#include <cuda_fp16.h>
#include <mma.h>

using namespace nvcuda;

#define VOCAB  32000
#define EMBED  512
#define HIDDEN 1024
#define BATCH  64
#define SEQ    512
#define DGATE  4096
#define NTOK   (BATCH * SEQ)

// ---------------- device scratch (static; no allocation) ----------------
__device__ __half  g_xh[(size_t)NTOK * EMBED];      // gathered embeddings fp16 (row = t*64+b)
__device__ __half  g_wx[(size_t)EMBED * DGATE];     // x-weights fp16, col = h*4+gate (f,i,c,o)
__device__ __half  g_wh[(size_t)HIDDEN * DGATE];    // h-weights fp16, same col layout
__device__ float   g_bias[DGATE];                   // interleaved biases
__device__ float   g_pre[(size_t)NTOK * DGATE];     // precomputed x-projections fp32
__device__ __half  g_wout[(size_t)HIDDEN * VOCAB];  // Wout fp16
__device__ __half  g_h[2][BATCH * HIDDEN];          // h double buffer fp16
__device__ unsigned g_flag[128];                    // grid barrier flags (one per CTA)

// ---------------- helpers ----------------
__device__ __forceinline__ void cp_async16(void* smem, const void* gmem) {
    unsigned s = (unsigned)__cvta_generic_to_shared(smem);
    asm volatile("cp.async.cg.shared.global [%0], [%1], 16;\n" :: "r"(s), "l"(gmem));
}
__device__ __forceinline__ void cp_commit() { asm volatile("cp.async.commit_group;\n"); }
template <int N> __device__ __forceinline__ void cp_wait() {
    asm volatile("cp.async.wait_group %0;\n" :: "n"(N));
}
__device__ __forceinline__ float sigf(float x) { return 1.f / (1.f + __expf(-x)); }

// ---------------- init: zero h buffers + barrier flags ----------------
__global__ void k_init() {
    int i = blockIdx.x * blockDim.x + threadIdx.x;
    if (i < 128) g_flag[i] = 0;
    __half* h = &g_h[0][0];
    const int n = 2 * BATCH * HIDDEN;
    for (; i < n; i += gridDim.x * blockDim.x) h[i] = __float2half(0.f);
}

// ---------------- weight conversion (gate interleave, fp16) ----------------
__global__ void k_convw(const float* __restrict__ Wf, const float* __restrict__ Wi,
                        const float* __restrict__ Wc, const float* __restrict__ Wo,
                        const float* __restrict__ bf, const float* __restrict__ bi,
                        const float* __restrict__ bc, const float* __restrict__ bo) {
    int i = blockIdx.x * blockDim.x + threadIdx.x;   // over 1536*1024
    if (i >= (EMBED + HIDDEN) * HIDDEN) return;
    int k = i >> 10, h = i & 1023;
    size_t src = (size_t)k * HIDDEN + h;
    __half2 lo = __floats2half2_rn(Wf[src], Wi[src]);
    __half2 hi = __floats2half2_rn(Wc[src], Wo[src]);
    __half2* dst;
    if (k < EMBED) dst = (__half2*)(g_wx + (size_t)k * DGATE + h * 4);
    else           dst = (__half2*)(g_wh + (size_t)(k - EMBED) * DGATE + h * 4);
    dst[0] = lo; dst[1] = hi;
    if (i < HIDDEN) {
        g_bias[i * 4 + 0] = bf[i]; g_bias[i * 4 + 1] = bi[i];
        g_bias[i * 4 + 2] = bc[i]; g_bias[i * 4 + 3] = bo[i];
    }
}

__global__ void k_convwout(const float* __restrict__ Wout) {
    size_t stride = (size_t)gridDim.x * blockDim.x;
    size_t npair = (size_t)HIDDEN * VOCAB / 2;
    for (size_t i = blockIdx.x * (size_t)blockDim.x + threadIdx.x; i < npair; i += stride) {
        float2 v = ((const float2*)Wout)[i];
        ((__half2*)g_wout)[i] = __floats2half2_rn(v.x, v.y);
    }
}

// ---------------- embedding gather (row = t*64 + b), 8 halfs/thread ----------------
__global__ void k_gather(const int* __restrict__ ids, const float* __restrict__ emb) {
    int i = blockIdx.x * blockDim.x + threadIdx.x;   // over NTOK * (EMBED/8)
    int r = i >> 6, seg = i & 63;
    int t = r >> 6, b = r & 63;
    int tok = ids[b * SEQ + t];
    const float4* s = (const float4*)(emb + (size_t)tok * EMBED + seg * 8);
    float4 v0 = s[0], v1 = s[1];
    __half2 h01 = __floats2half2_rn(v0.x, v0.y);
    __half2 h23 = __floats2half2_rn(v0.z, v0.w);
    __half2 h45 = __floats2half2_rn(v1.x, v1.y);
    __half2 h67 = __floats2half2_rn(v1.z, v1.w);
    uint4 pack;
    pack.x = *(unsigned*)&h01; pack.y = *(unsigned*)&h23;
    pack.z = *(unsigned*)&h45; pack.w = *(unsigned*)&h67;
    *(uint4*)(g_xh + (size_t)i * 8) = pack;
}

// ---------------- phase 1: Pre = Xh @ Wx  (M=32768, N=4096, K=512) ----------------
__global__ void __launch_bounds__(256, 1) k_gemm1() {
    extern __shared__ char smem[];
    __half* As = (__half*)smem;                              // [2][128][72]
    __half* Bs = (__half*)(smem + 2 * 128 * 72 * 2);         // [2][64][264]
    const int n0 = blockIdx.x * 256;
    const int m0 = blockIdx.y * 128;
    const int tid = threadIdx.x;
    const int w = tid >> 5;
    const int wm = w & 1, wn = w >> 1;

    wmma::fragment<wmma::accumulator, 16, 16, 16, float> acc[4][4];
#pragma unroll
    for (int i = 0; i < 4; i++)
#pragma unroll
        for (int j = 0; j < 4; j++) wmma::fill_fragment(acc[i][j], 0.f);

    auto loadAB = [&](int buf, int kc) {
        __half* a = As + buf * (128 * 72);
        __half* b = Bs + buf * (64 * 264);
        const __half* gA = g_xh + (size_t)m0 * EMBED + kc * 64;
        const __half* gB = g_wx + (size_t)(kc * 64) * DGATE + n0;
#pragma unroll
        for (int i = tid; i < 1024; i += 256) {
            int r = i >> 3, c = i & 7;
            cp_async16(a + r * 72 + c * 8, gA + (size_t)r * EMBED + c * 8);
        }
#pragma unroll
        for (int i = tid; i < 2048; i += 256) {
            int r = i >> 5, c = i & 31;
            cp_async16(b + r * 264 + c * 8, gB + (size_t)r * DGATE + c * 8);
        }
    };

    loadAB(0, 0);
    cp_commit();
    const int KC = EMBED / 64;   // 8
    for (int kc = 0; kc < KC; ++kc) {
        if (kc + 1 < KC) { loadAB((kc + 1) & 1, kc + 1); cp_commit(); cp_wait<1>(); }
        else             { cp_wait<0>(); }
        __syncthreads();
        const __half* a = As + (kc & 1) * (128 * 72) + wm * 64 * 72;
        const __half* b = Bs + (kc & 1) * (64 * 264) + wn * 64;
#pragma unroll
        for (int kk = 0; kk < 4; ++kk) {
            wmma::fragment<wmma::matrix_a, 16, 16, 16, __half, wmma::row_major> fa[4];
            wmma::fragment<wmma::matrix_b, 16, 16, 16, __half, wmma::row_major> fb[4];
#pragma unroll
            for (int i = 0; i < 4; i++) wmma::load_matrix_sync(fa[i], a + i * 16 * 72 + kk * 16, 72);
#pragma unroll
            for (int j = 0; j < 4; j++) wmma::load_matrix_sync(fb[j], b + kk * 16 * 264 + j * 16, 264);
#pragma unroll
            for (int i = 0; i < 4; i++)
#pragma unroll
                for (int j = 0; j < 4; j++) wmma::mma_sync(acc[i][j], fa[i], fb[j], acc[i][j]);
        }
        __syncthreads();
    }
#pragma unroll
    for (int i = 0; i < 4; i++)
#pragma unroll
        for (int j = 0; j < 4; j++) {
            float* dst = g_pre + (size_t)(m0 + wm * 64 + i * 16) * DGATE + n0 + wn * 64 + j * 16;
            wmma::store_matrix_sync(dst, acc[i][j], DGATE, wmma::mem_row_major);
        }
}

// ---------------- persistent recurrence ----------------
// 128 CTAs; CTA owns gate cols [cta*32, cta*32+32) = hidden units [cta*8, cta*8+8).
// Per step: each warp cp.asyncs its own 64x128 K-slice of h (no CTA sync),
// runs its K-chunk MMAs, stores fp32 partials aliased over its own h slice,
// ONE __syncthreads, fused reduce+gates+update, vectorized h writeback,
// flag-array grid barrier.
__global__ void __launch_bounds__(256, 1) k_rnn() {
    extern __shared__ char smem[];
    __half* ws   = (__half*)smem;                               // [1024][40]  81920 B
    __half* hs   = (__half*)(smem + 81920);                     // 8 x [64][136] = 139264 B
    float*  bias = (float*)(smem + 81920 + 139264);             // [32]         128 B
    __half* hout = (__half*)(smem + 81920 + 139264 + 128);      // [64][8]     1024 B
    const int cta  = blockIdx.x;
    const int n0   = cta * 32;
    const int tid  = threadIdx.x;
    const int w    = tid >> 5;
    const int lane = tid & 31;
    __half* hs_w = hs + w * 8704;            // this warp's 64x136-half slice
    float*  partBase = (float*)hs;           // partials alias h slices (4352 floats/warp)

    // one-time: load Wh slice (padded ldm=40) + bias
    for (int i = tid; i < 1024 * 4; i += 256) {
        int k = i >> 2, j = (i & 3) * 8;
        *(float4*)(ws + k * 40 + j) = *(const float4*)(g_wh + (size_t)k * DGATE + n0 + j);
    }
    if (tid < 32) bias[tid] = g_bias[n0 + tid];
    __syncthreads();

    float cst0 = 0.f, cst1 = 0.f;
    const int b0 = tid >> 3, hu0 = tid & 7;
    const int b1 = (tid + 256) >> 3, hu1 = tid & 7;

#pragma unroll 1
    for (int t = 0; t < SEQ; ++t) {
        const __half* hsrc = g_h[t & 1];
        __half*       hdst = g_h[(t + 1) & 1];

        // prefetch gate pre-activations (independent of h) to hide DRAM latency
        const float* pret = g_pre + (size_t)t * BATCH * DGATE;
        float4 pr0 = __ldg((const float4*)(pret + (size_t)b0 * DGATE + n0 + hu0 * 4));
        float4 pr1 = __ldg((const float4*)(pret + (size_t)b1 * DGATE + n0 + hu1 * 4));

        // per-warp load of its own K slice: 64 rows x 128 halfs
        {
            const __half* src = hsrc + w * 128;
#pragma unroll
            for (int i = lane; i < 64 * 16; i += 32) {
                int r = i >> 4, c = i & 15;
                cp_async16(hs_w + r * 136 + c * 8, src + (size_t)r * HIDDEN + c * 8);
            }
            cp_commit();
            cp_wait<0>();
            __syncwarp();
        }

        wmma::fragment<wmma::accumulator, 16, 16, 16, float> acc[4][2];
#pragma unroll
        for (int i = 0; i < 4; i++) {
            wmma::fill_fragment(acc[i][0], 0.f);
            wmma::fill_fragment(acc[i][1], 0.f);
        }

#pragma unroll
        for (int kk = 0; kk < 8; ++kk) {
            wmma::fragment<wmma::matrix_a, 16, 16, 16, __half, wmma::row_major> fa[4];
            wmma::fragment<wmma::matrix_b, 16, 16, 16, __half, wmma::row_major> fb[2];
#pragma unroll
            for (int i = 0; i < 4; i++)
                wmma::load_matrix_sync(fa[i], hs_w + i * 16 * 136 + kk * 16, 136);
#pragma unroll
            for (int j = 0; j < 2; j++)
                wmma::load_matrix_sync(fb[j], ws + (size_t)(w * 128 + kk * 16) * 40 + j * 16, 40);
#pragma unroll
            for (int i = 0; i < 4; i++) {
                wmma::mma_sync(acc[i][0], fa[i], fb[0], acc[i][0]);
                wmma::mma_sync(acc[i][1], fa[i], fb[1], acc[i][1]);
            }
        }

        // store partials over this warp's own (fully consumed) h slice
        float* part_w = partBase + w * 4352;
#pragma unroll
        for (int i = 0; i < 4; i++) {
            wmma::store_matrix_sync(part_w + i * 16 * 32,      acc[i][0], 32, wmma::mem_row_major);
            wmma::store_matrix_sync(part_w + i * 16 * 32 + 16, acc[i][1], 32, wmma::mem_row_major);
        }
        __syncthreads();

        // fused reduce + gates + state update (pairs tid and tid+256)
        {
            float4 bb = *(const float4*)(bias + hu0 * 4);
            float xf = pr0.x + bb.x, xi = pr0.y + bb.y, xg = pr0.z + bb.z, xo = pr0.w + bb.w;
#pragma unroll
            for (int ww = 0; ww < 8; ++ww) {
                float4 q = *(const float4*)(partBase + ww * 4352 + b0 * 32 + hu0 * 4);
                xf += q.x; xi += q.y; xg += q.z; xo += q.w;
            }
            float f = sigf(xf), ii = sigf(xi), g = tanhf(xg), o = sigf(xo);
            cst0 = cst0 * f + g * ii;
            hout[b0 * 8 + hu0] = __float2half(cst0 * o);
        }
        {
            float4 bb = *(const float4*)(bias + hu1 * 4);
            float xf = pr1.x + bb.x, xi = pr1.y + bb.y, xg = pr1.z + bb.z, xo = pr1.w + bb.w;
#pragma unroll
            for (int ww = 0; ww < 8; ++ww) {
                float4 q = *(const float4*)(partBase + ww * 4352 + b1 * 32 + hu1 * 4);
                xf += q.x; xi += q.y; xg += q.z; xo += q.w;
            }
            float f = sigf(xf), ii = sigf(xi), g = tanhf(xg), o = sigf(xo);
            cst1 = cst1 * f + g * ii;
            hout[b1 * 8 + hu1] = __float2half(cst1 * o);
        }
        __syncthreads();

        // vectorized h writeback: one 16B store per batch row
        if (tid < 64)
            *(uint4*)(hdst + (size_t)tid * HIDDEN + cta * 8) = *(const uint4*)(hout + tid * 8);

        // grid barrier: flag array, release-acquire
        __threadfence();
        __syncthreads();
        if (tid == 0) ((volatile unsigned*)g_flag)[cta] = (unsigned)(t + 1);
        if (tid < 128) {
            while (((volatile unsigned*)g_flag)[tid] < (unsigned)(t + 1)) { }
        }
        __threadfence();
        __syncthreads();
    }
}

// ---------------- readout: logits = h_final @ Wout + bout ----------------
__global__ void __launch_bounds__(256, 1) k_readout(const float* __restrict__ bout,
                                                    float* __restrict__ out) {
    extern __shared__ char smem[];
    __half* hsm   = (__half*)smem;                  // [64][1032]  132096 B
    float*  stage = (float*)(smem + 132096);        // [64][132]   33792 B
    const int n0 = blockIdx.x * 128;
    const int tid = threadIdx.x;
    const int w = tid >> 5;
    const __half* hfin = g_h[0];   // final h after SEQ=512 steps

    for (int i = tid; i < 64 * 128; i += 256) {
        int r = i >> 7, c = i & 127;
        *(float4*)(hsm + r * 1032 + c * 8) = *(const float4*)(hfin + (size_t)r * HIDDEN + c * 8);
    }
    __syncthreads();

    wmma::fragment<wmma::accumulator, 16, 16, 16, float> acc[4];
#pragma unroll
    for (int i = 0; i < 4; i++) wmma::fill_fragment(acc[i], 0.f);

#pragma unroll 1
    for (int kk = 0; kk < 64; ++kk) {
        wmma::fragment<wmma::matrix_a, 16, 16, 16, __half, wmma::row_major> fa;
        wmma::fragment<wmma::matrix_b, 16, 16, 16, __half, wmma::row_major> fb;
        wmma::load_matrix_sync(fb, g_wout + (size_t)(kk * 16) * VOCAB + n0 + w * 16, VOCAB);
#pragma unroll
        for (int i = 0; i < 4; i++) {
            wmma::load_matrix_sync(fa, hsm + i * 16 * 1032 + kk * 16, 1032);
            wmma::mma_sync(acc[i], fa, fb, acc[i]);
        }
    }
#pragma unroll
    for (int i = 0; i < 4; i++)
        wmma::store_matrix_sync(stage + i * 16 * 132 + w * 16, acc[i], 132, wmma::mem_row_major);
    __syncthreads();

    for (int i = tid; i < 64 * 128; i += 256) {
        int r = i >> 7, c = i & 127;
        out[(size_t)r * VOCAB + n0 + c] = stage[r * 132 + c] + bout[n0 + c];
    }
}

// ---------------- launch ----------------
extern "C" void kernel_launch(void* const* d_in, const int* in_sizes, int n_in,
                              void* d_out, int out_size) {
    const int*   ids  = (const int*)d_in[0];
    const float* emb  = (const float*)d_in[1];
    const float* Wf   = (const float*)d_in[2];
    const float* bf   = (const float*)d_in[3];
    const float* Wi   = (const float*)d_in[4];
    const float* bi   = (const float*)d_in[5];
    const float* Wc   = (const float*)d_in[6];
    const float* bc   = (const float*)d_in[7];
    const float* Wo   = (const float*)d_in[8];
    const float* bo   = (const float*)d_in[9];
    const float* Wout = (const float*)d_in[10];
    const float* bout = (const float*)d_in[11];
    float* out = (float*)d_out;

    const int smem1 = 2 * 128 * 72 * 2 + 2 * 64 * 264 * 2;            // 104448
    const int smemR = 81920 + 139264 + 128 + 1024;                    // 222336
    const int smemO = 64 * 1032 * 2 + 64 * 132 * 4;                   // 165888
    cudaFuncSetAttribute(k_gemm1,   cudaFuncAttributeMaxDynamicSharedMemorySize, smem1);
    cudaFuncSetAttribute(k_rnn,     cudaFuncAttributeMaxDynamicSharedMemorySize, smemR);
    cudaFuncSetAttribute(k_readout, cudaFuncAttributeMaxDynamicSharedMemorySize, smemO);

    k_init<<<256, 256>>>();
    k_convw<<<(1536 * 1024 + 255) / 256, 256>>>(Wf, Wi, Wc, Wo, bf, bi, bc, bo);
    k_convwout<<<8192, 256>>>(Wout);
    k_gather<<<NTOK * (EMBED / 8) / 256, 256>>>(ids, emb);
    k_gemm1<<<dim3(DGATE / 256, NTOK / 128), 256, smem1>>>();
    k_rnn<<<128, 256, smemR>>>();
    k_readout<<<VOCAB / 128, 256, smemO>>>(bout, out);
}

// round 5
// speedup vs baseline: 1.9439x; 1.9439x over previous
#include <cuda_runtime.h>
#include <cuda_fp16.h>
#include <mma.h>

using namespace nvcuda;

#define VOCAB  32000
#define EMBED  512
#define HIDDEN 1024
#define BATCH  64
#define SEQ    512
#define DGATE  4096
#define NTOK   (BATCH * SEQ)

// ---------------- device scratch (static; no allocation) ----------------
__device__ __half  g_xh[(size_t)NTOK * EMBED];      // gathered embeddings fp16 (row = t*64+b)
__device__ __half  g_wx[(size_t)EMBED * DGATE];     // x-weights fp16, col = h*4+gate (f,i,c,o)
__device__ __half  g_wh[(size_t)HIDDEN * DGATE];    // h-weights fp16, same col layout
__device__ float   g_bias[DGATE];                   // interleaved biases
__device__ float   g_pre[(size_t)NTOK * DGATE];     // precomputed x-projections fp32
__device__ __half  g_wout[(size_t)HIDDEN * VOCAB];  // Wout fp16
__device__ __half  g_h[2][BATCH * HIDDEN];          // h double buffer fp16
__device__ unsigned g_bar;                          // grid barrier counter

// ---------------- helpers ----------------
__device__ __forceinline__ void cp_async16(void* smem, const void* gmem) {
    unsigned s = (unsigned)__cvta_generic_to_shared(smem);
    asm volatile("cp.async.cg.shared.global [%0], [%1], 16;\n" :: "r"(s), "l"(gmem));
}
__device__ __forceinline__ void cp_commit() { asm volatile("cp.async.commit_group;\n"); }
template <int N> __device__ __forceinline__ void cp_wait() {
    asm volatile("cp.async.wait_group %0;\n" :: "n"(N));
}
__device__ __forceinline__ float sigf(float x) { return 1.f / (1.f + __expf(-x)); }

// ---------------- init: zero h buffers + barrier ----------------
__global__ void k_init() {
    int i = blockIdx.x * blockDim.x + threadIdx.x;
    if (i == 0) g_bar = 0;
    __half* h = &g_h[0][0];
    const int n = 2 * BATCH * HIDDEN;
    for (; i < n; i += gridDim.x * blockDim.x) h[i] = __float2half(0.f);
}

// ---------------- weight conversion (gate interleave, fp16) ----------------
__global__ void k_convw(const float* __restrict__ Wf, const float* __restrict__ Wi,
                        const float* __restrict__ Wc, const float* __restrict__ Wo,
                        const float* __restrict__ bf, const float* __restrict__ bi,
                        const float* __restrict__ bc, const float* __restrict__ bo) {
    int i = blockIdx.x * blockDim.x + threadIdx.x;   // over 1536*1024
    if (i >= (EMBED + HIDDEN) * HIDDEN) return;
    int k = i >> 10, h = i & 1023;
    size_t src = (size_t)k * HIDDEN + h;
    __half2 lo = __floats2half2_rn(Wf[src], Wi[src]);
    __half2 hi = __floats2half2_rn(Wc[src], Wo[src]);
    __half2* dst;
    if (k < EMBED) dst = (__half2*)(g_wx + (size_t)k * DGATE + h * 4);
    else           dst = (__half2*)(g_wh + (size_t)(k - EMBED) * DGATE + h * 4);
    dst[0] = lo; dst[1] = hi;
    if (i < HIDDEN) {
        g_bias[i * 4 + 0] = bf[i]; g_bias[i * 4 + 1] = bi[i];
        g_bias[i * 4 + 2] = bc[i]; g_bias[i * 4 + 3] = bo[i];
    }
}

__global__ void k_convwout(const float* __restrict__ Wout) {
    size_t stride = (size_t)gridDim.x * blockDim.x;
    size_t npair = (size_t)HIDDEN * VOCAB / 2;
    for (size_t i = blockIdx.x * (size_t)blockDim.x + threadIdx.x; i < npair; i += stride) {
        float2 v = ((const float2*)Wout)[i];
        ((__half2*)g_wout)[i] = __floats2half2_rn(v.x, v.y);
    }
}

// ---------------- embedding gather (row = t*64 + b), 8 halfs/thread ----------------
__global__ void k_gather(const int* __restrict__ ids, const float* __restrict__ emb) {
    int i = blockIdx.x * blockDim.x + threadIdx.x;   // over NTOK * (EMBED/8)
    int r = i >> 6, seg = i & 63;
    int t = r >> 6, b = r & 63;
    int tok = ids[b * SEQ + t];
    const float4* s = (const float4*)(emb + (size_t)tok * EMBED + seg * 8);
    float4 v0 = s[0], v1 = s[1];
    __half2 h01 = __floats2half2_rn(v0.x, v0.y);
    __half2 h23 = __floats2half2_rn(v0.z, v0.w);
    __half2 h45 = __floats2half2_rn(v1.x, v1.y);
    __half2 h67 = __floats2half2_rn(v1.z, v1.w);
    uint4 pack;
    pack.x = *(unsigned*)&h01; pack.y = *(unsigned*)&h23;
    pack.z = *(unsigned*)&h45; pack.w = *(unsigned*)&h67;
    *(uint4*)(g_xh + (size_t)i * 8) = pack;
}

// ---------------- phase 1: Pre = Xh @ Wx  (M=32768, N=4096, K=512) ----------------
__global__ void __launch_bounds__(256, 1) k_gemm1() {
    extern __shared__ char smem[];
    __half* As = (__half*)smem;                              // [2][128][72]
    __half* Bs = (__half*)(smem + 2 * 128 * 72 * 2);         // [2][64][264]
    const int n0 = blockIdx.x * 256;
    const int m0 = blockIdx.y * 128;
    const int tid = threadIdx.x;
    const int w = tid >> 5;
    const int wm = w & 1, wn = w >> 1;

    wmma::fragment<wmma::accumulator, 16, 16, 16, float> acc[4][4];
#pragma unroll
    for (int i = 0; i < 4; i++)
#pragma unroll
        for (int j = 0; j < 4; j++) wmma::fill_fragment(acc[i][j], 0.f);

    auto loadAB = [&](int buf, int kc) {
        __half* a = As + buf * (128 * 72);
        __half* b = Bs + buf * (64 * 264);
        const __half* gA = g_xh + (size_t)m0 * EMBED + kc * 64;
        const __half* gB = g_wx + (size_t)(kc * 64) * DGATE + n0;
#pragma unroll
        for (int i = tid; i < 1024; i += 256) {
            int r = i >> 3, c = i & 7;
            cp_async16(a + r * 72 + c * 8, gA + (size_t)r * EMBED + c * 8);
        }
#pragma unroll
        for (int i = tid; i < 2048; i += 256) {
            int r = i >> 5, c = i & 31;
            cp_async16(b + r * 264 + c * 8, gB + (size_t)r * DGATE + c * 8);
        }
    };

    loadAB(0, 0);
    cp_commit();
    const int KC = EMBED / 64;   // 8
    for (int kc = 0; kc < KC; ++kc) {
        if (kc + 1 < KC) { loadAB((kc + 1) & 1, kc + 1); cp_commit(); cp_wait<1>(); }
        else             { cp_wait<0>(); }
        __syncthreads();
        const __half* a = As + (kc & 1) * (128 * 72) + wm * 64 * 72;
        const __half* b = Bs + (kc & 1) * (64 * 264) + wn * 64;
#pragma unroll
        for (int kk = 0; kk < 4; ++kk) {
            wmma::fragment<wmma::matrix_a, 16, 16, 16, __half, wmma::row_major> fa[4];
            wmma::fragment<wmma::matrix_b, 16, 16, 16, __half, wmma::row_major> fb[4];
#pragma unroll
            for (int i = 0; i < 4; i++) wmma::load_matrix_sync(fa[i], a + i * 16 * 72 + kk * 16, 72);
#pragma unroll
            for (int j = 0; j < 4; j++) wmma::load_matrix_sync(fb[j], b + kk * 16 * 264 + j * 16, 264);
#pragma unroll
            for (int i = 0; i < 4; i++)
#pragma unroll
                for (int j = 0; j < 4; j++) wmma::mma_sync(acc[i][j], fa[i], fb[j], acc[i][j]);
        }
        __syncthreads();
    }
#pragma unroll
    for (int i = 0; i < 4; i++)
#pragma unroll
        for (int j = 0; j < 4; j++) {
            float* dst = g_pre + (size_t)(m0 + wm * 64 + i * 16) * DGATE + n0 + wn * 64 + j * 16;
            wmma::store_matrix_sync(dst, acc[i][j], DGATE, wmma::mem_row_major);
        }
}

// ---------------- persistent recurrence ----------------
// 128 CTAs; CTA owns gate cols [cta*32, cta*32+32) = hidden units [cta*8, cta*8+8).
// Per step: 4 double-buffered K-chunks of 256; warp w handles k-rows
// [chunk*256 + w*32, +32) of each chunk -> accumulates over chunks; 8-way
// K-split partials reduced in fused epilogue. Round-3 atomic grid barrier.
__global__ void __launch_bounds__(256, 1) k_rnn() {
    extern __shared__ char smem[];
    __half* ws   = (__half*)smem;                          // [1024][40]   81920 B
    __half* hs   = (__half*)(smem + 81920);                // [2][64][264] 67584 B
    float*  part = (float*)(smem + 81920 + 67584);         // [8][64][32]  65536 B
    float*  bias = (float*)(smem + 81920 + 67584 + 65536); // [32]
    const int cta = blockIdx.x;
    const int n0  = cta * 32;
    const int tid = threadIdx.x;
    const int w   = tid >> 5;

    // one-time: Wh slice (padded ldm=40) + bias
    for (int i = tid; i < 1024 * 4; i += 256) {
        int k = i >> 2, j = (i & 3) * 8;
        *(float4*)(ws + k * 40 + j) = *(const float4*)(g_wh + (size_t)k * DGATE + n0 + j);
    }
    if (tid < 32) bias[tid] = g_bias[n0 + tid];
    __syncthreads();

    float cst0 = 0.f, cst1 = 0.f;
    const int b0 = tid >> 3, hu0 = tid & 7;
    const int b1 = (tid + 256) >> 3, hu1 = tid & 7;

#pragma unroll 1
    for (int t = 0; t < SEQ; ++t) {
        const __half* hsrc = g_h[t & 1];
        __half*       hdst = g_h[(t + 1) & 1];

        // prefetch gate pre-activations (independent of h pipeline)
        const float* pret = g_pre + (size_t)t * BATCH * DGATE;
        float4 pr0 = __ldg((const float4*)(pret + (size_t)b0 * DGATE + n0 + hu0 * 4));
        float4 pr1 = __ldg((const float4*)(pret + (size_t)b1 * DGATE + n0 + hu1 * 4));

        wmma::fragment<wmma::accumulator, 16, 16, 16, float> acc[4][2];
#pragma unroll
        for (int i = 0; i < 4; i++) {
            wmma::fill_fragment(acc[i][0], 0.f);
            wmma::fill_fragment(acc[i][1], 0.f);
        }

        // prologue: k-chunk 0 (256 cols) into buffer 0
#pragma unroll
        for (int i = tid; i < 2048; i += 256) {
            int r = i >> 5, c = i & 31;
            cp_async16(hs + r * 264 + c * 8, hsrc + (size_t)r * HIDDEN + c * 8);
        }
        cp_commit();

#pragma unroll 1
        for (int kc = 0; kc < 4; ++kc) {
            if (kc < 3) {
                __half* dst = hs + ((kc + 1) & 1) * (64 * 264);
                const __half* src = hsrc + (kc + 1) * 256;
#pragma unroll
                for (int i = tid; i < 2048; i += 256) {
                    int r = i >> 5, c = i & 31;
                    cp_async16(dst + r * 264 + c * 8, src + (size_t)r * HIDDEN + c * 8);
                }
                cp_commit(); cp_wait<1>();
            } else cp_wait<0>();
            __syncthreads();
            const __half* hb = hs + (kc & 1) * (64 * 264);
            // warp w covers k-local [w*32, w*32+32) = 2 k-frags
#pragma unroll
            for (int kk = 0; kk < 2; ++kk) {
                wmma::fragment<wmma::matrix_a, 16, 16, 16, __half, wmma::row_major> fa[4];
                wmma::fragment<wmma::matrix_b, 16, 16, 16, __half, wmma::row_major> fb[2];
#pragma unroll
                for (int i = 0; i < 4; i++)
                    wmma::load_matrix_sync(fa[i], hb + i * 16 * 264 + w * 32 + kk * 16, 264);
#pragma unroll
                for (int j = 0; j < 2; j++)
                    wmma::load_matrix_sync(fb[j], ws + (size_t)(kc * 256 + w * 32 + kk * 16) * 40 + j * 16, 40);
#pragma unroll
                for (int i = 0; i < 4; i++) {
                    wmma::mma_sync(acc[i][0], fa[i], fb[0], acc[i][0]);
                    wmma::mma_sync(acc[i][1], fa[i], fb[1], acc[i][1]);
                }
            }
            __syncthreads();
        }

        // K-split partials to SMEM
#pragma unroll
        for (int i = 0; i < 4; i++) {
            wmma::store_matrix_sync(part + w * 2048 + i * 16 * 32,      acc[i][0], 32, wmma::mem_row_major);
            wmma::store_matrix_sync(part + w * 2048 + i * 16 * 32 + 16, acc[i][1], 32, wmma::mem_row_major);
        }
        __syncthreads();

        // fused reduce + gates + state update (pairs tid and tid+256)
        {
            float4 bb = *(const float4*)(bias + hu0 * 4);
            float xf = pr0.x + bb.x, xi = pr0.y + bb.y, xg = pr0.z + bb.z, xo = pr0.w + bb.w;
#pragma unroll
            for (int ww = 0; ww < 8; ++ww) {
                float4 q = *(const float4*)(part + ww * 2048 + b0 * 32 + hu0 * 4);
                xf += q.x; xi += q.y; xg += q.z; xo += q.w;
            }
            float f = sigf(xf), ii = sigf(xi), g = tanhf(xg), o = sigf(xo);
            cst0 = cst0 * f + g * ii;
            hdst[b0 * HIDDEN + cta * 8 + hu0] = __float2half(cst0 * o);
        }
        {
            float4 bb = *(const float4*)(bias + hu1 * 4);
            float xf = pr1.x + bb.x, xi = pr1.y + bb.y, xg = pr1.z + bb.z, xo = pr1.w + bb.w;
#pragma unroll
            for (int ww = 0; ww < 8; ++ww) {
                float4 q = *(const float4*)(part + ww * 2048 + b1 * 32 + hu1 * 4);
                xf += q.x; xi += q.y; xg += q.z; xo += q.w;
            }
            float f = sigf(xf), ii = sigf(xi), g = tanhf(xg), o = sigf(xo);
            cst1 = cst1 * f + g * ii;
            hdst[b1 * HIDDEN + cta * 8 + hu1] = __float2half(cst1 * o);
        }

        // grid barrier (round-3 style: single spinner per CTA)
        __threadfence();
        __syncthreads();
        if (tid == 0) {
            atomicAdd(&g_bar, 1u);
            unsigned target = (unsigned)(t + 1) * gridDim.x;
            while (*(volatile unsigned*)&g_bar < target) { }
        }
        __syncthreads();
    }
}

// ---------------- readout: logits = h_final @ Wout + bout ----------------
__global__ void __launch_bounds__(256, 1) k_readout(const float* __restrict__ bout,
                                                    float* __restrict__ out) {
    extern __shared__ char smem[];
    __half* hsm   = (__half*)smem;                  // [64][1032]  132096 B
    float*  stage = (float*)(smem + 132096);        // [64][132]   33792 B
    const int n0 = blockIdx.x * 128;
    const int tid = threadIdx.x;
    const int w = tid >> 5;
    const __half* hfin = g_h[0];   // final h after SEQ=512 steps

    for (int i = tid; i < 64 * 128; i += 256) {
        int r = i >> 7, c = i & 127;
        *(float4*)(hsm + r * 1032 + c * 8) = *(const float4*)(hfin + (size_t)r * HIDDEN + c * 8);
    }
    __syncthreads();

    wmma::fragment<wmma::accumulator, 16, 16, 16, float> acc[4];
#pragma unroll
    for (int i = 0; i < 4; i++) wmma::fill_fragment(acc[i], 0.f);

#pragma unroll 1
    for (int kk = 0; kk < 64; ++kk) {
        wmma::fragment<wmma::matrix_a, 16, 16, 16, __half, wmma::row_major> fa;
        wmma::fragment<wmma::matrix_b, 16, 16, 16, __half, wmma::row_major> fb;
        wmma::load_matrix_sync(fb, g_wout + (size_t)(kk * 16) * VOCAB + n0 + w * 16, VOCAB);
#pragma unroll
        for (int i = 0; i < 4; i++) {
            wmma::load_matrix_sync(fa, hsm + i * 16 * 1032 + kk * 16, 1032);
            wmma::mma_sync(acc[i], fa, fb, acc[i]);
        }
    }
#pragma unroll
    for (int i = 0; i < 4; i++)
        wmma::store_matrix_sync(stage + i * 16 * 132 + w * 16, acc[i], 132, wmma::mem_row_major);
    __syncthreads();

    for (int i = tid; i < 64 * 128; i += 256) {
        int r = i >> 7, c = i & 127;
        out[(size_t)r * VOCAB + n0 + c] = stage[r * 132 + c] + bout[n0 + c];
    }
}

// ---------------- launch ----------------
extern "C" void kernel_launch(void* const* d_in, const int* in_sizes, int n_in,
                              void* d_out, int out_size) {
    const int*   ids  = (const int*)d_in[0];
    const float* emb  = (const float*)d_in[1];
    const float* Wf   = (const float*)d_in[2];
    const float* bf   = (const float*)d_in[3];
    const float* Wi   = (const float*)d_in[4];
    const float* bi   = (const float*)d_in[5];
    const float* Wc   = (const float*)d_in[6];
    const float* bc   = (const float*)d_in[7];
    const float* Wo   = (const float*)d_in[8];
    const float* bo   = (const float*)d_in[9];
    const float* Wout = (const float*)d_in[10];
    const float* bout = (const float*)d_in[11];
    float* out = (float*)d_out;

    const int smem1 = 2 * 128 * 72 * 2 + 2 * 64 * 264 * 2;            // 104448
    const int smemR = 81920 + 67584 + 65536 + 128;                    // 215168
    const int smemO = 64 * 1032 * 2 + 64 * 132 * 4;                   // 165888
    cudaFuncSetAttribute(k_gemm1,   cudaFuncAttributeMaxDynamicSharedMemorySize, smem1);
    cudaFuncSetAttribute(k_rnn,     cudaFuncAttributeMaxDynamicSharedMemorySize, smemR);
    cudaFuncSetAttribute(k_readout, cudaFuncAttributeMaxDynamicSharedMemorySize, smemO);

    k_init<<<256, 256>>>();
    k_convw<<<(1536 * 1024 + 255) / 256, 256>>>(Wf, Wi, Wc, Wo, bf, bi, bc, bo);
    k_convwout<<<8192, 256>>>(Wout);
    k_gather<<<NTOK * (EMBED / 8) / 256, 256>>>(ids, emb);
    k_gemm1<<<dim3(DGATE / 256, NTOK / 128), 256, smem1>>>();
    k_rnn<<<128, 256, smemR>>>();
    k_readout<<<VOCAB / 128, 256, smemO>>>(bout, out);
}